// round 5
// baseline (speedup 1.0000x reference)
#include <cuda_runtime.h>
#include <cstdint>
#include <cstddef>

#define N_NODES 20000
#define N_EDGES 320000
#define EPB 8

#define LOG2_C       0.6931471805599453f
#define INV_SQRT3_C  0.5773502691896258f
#define INV_SQRT8_C  0.35355339059327373f
#define W_SCALE      0.125f
#define INV_MUL_C    0.125f
#define SC_A_C       0.02209708691207961f   // 1/sqrt(128) * 1/sqrt(16)
#define SC_B_C       0.04419417382415922f   // 1/sqrt(512)

__device__ __align__(1024) float d_sv[(size_t)N_NODES * 256];
__device__ __align__(1024) float d_agg[(size_t)N_NODES * 512];

__device__ __forceinline__ unsigned smem_u32(const void* p) {
    return (unsigned)__cvta_generic_to_shared(p);
}
__device__ __forceinline__ float4 ld4s(const float* p) {
    return *reinterpret_cast<const float4*>(p);
}
__device__ __forceinline__ float2 ld2s(const float* p) {
    return *reinterpret_cast<const float2*>(p);
}

// ---------------------------------------------------------------------------
__global__ void zero_agg_kernel() {
    size_t i = (size_t)blockIdx.x * blockDim.x + threadIdx.x;
    float4* p = reinterpret_cast<float4*>(d_agg);
    if (i < (size_t)N_NODES * 128) p[i] = make_float4(0.f, 0.f, 0.f, 0.f);
}

// ---------------------------------------------------------------------------
// node prep: s = s0 @ W1s ; v = v0 @ W1v  (per component), scaled 1/8
// ---------------------------------------------------------------------------
__global__ void __launch_bounds__(256)
nodeprep_kernel(const float* __restrict__ node_feat,
                const float* __restrict__ W1s,
                const float* __restrict__ W1v)
{
    __shared__ float sW1s[4096];
    __shared__ float sW1v[4096];
    __shared__ float sNF[4][256];

    const int tid = threadIdx.x;
    for (int i = tid; i < 4096; i += 256) { sW1s[i] = W1s[i]; sW1v[i] = W1v[i]; }
    __syncthreads();

    const int ngroups = (N_NODES + 3) / 4;
    for (int g = blockIdx.x; g < ngroups; g += gridDim.x) {
        const int n0 = g * 4;
        __syncthreads();
        for (int i = tid; i < 1024; i += 256) {
            const int nl = i >> 8, j = i & 255;
            const int n = n0 + nl;
            sNF[nl][j] = (n < N_NODES) ? node_feat[(size_t)n * 256 + j] : 0.f;
        }
        __syncthreads();
        const int nl = tid >> 6, w = tid & 63;
        const int n = n0 + nl;
        if (n < N_NODES) {
            float sacc = 0.f, v0a = 0.f, v1a = 0.f, v2a = 0.f;
#pragma unroll
            for (int u = 0; u < 64; ++u) {
                const float ws = sW1s[u * 64 + w];
                const float wv = sW1v[u * 64 + w];
                sacc = fmaf(sNF[nl][u], ws, sacc);
                v0a  = fmaf(sNF[nl][64 + 3 * u + 0], wv, v0a);
                v1a  = fmaf(sNF[nl][64 + 3 * u + 1], wv, v1a);
                v2a  = fmaf(sNF[nl][64 + 3 * u + 2], wv, v2a);
            }
            float* o = d_sv + (size_t)n * 256;
            o[w] = sacc * INV_MUL_C;
            o[64 + 3 * w + 0] = v0a * INV_MUL_C;
            o[64 + 3 * w + 1] = v1a * INV_MUL_C;
            o[64 + 3 * w + 2] = v2a * INV_MUL_C;
        }
    }
}

// ---------------------------------------------------------------------------
// edge kernel: fused FC1 -> softplus -> FC2 -> gather -> tensor product ->
// bulk-reduce scatter. EPB=8 edges per block iteration.
// ---------------------------------------------------------------------------
__global__ void __launch_bounds__(256, 2)
edge_kernel(const float* __restrict__ edge_sh,
            const float* __restrict__ edge_basis,
            const float* __restrict__ Wfc1,
            const float* __restrict__ Wfc2,
            const int*   __restrict__ edge_idx)
{
    __shared__ float sWfc1[512];
    __shared__ __align__(16) float sH[EPB][64];
    __shared__ __align__(16) float sOut[2][EPB][512];
    __shared__ int    sSrc[EPB];
    __shared__ int    sDst[EPB];
    __shared__ float4 sSh[EPB];

    const int tid = threadIdx.x;

    float wcol[64];
#pragma unroll
    for (int k = 0; k < 64; ++k) wcol[k] = Wfc2[k * 256 + tid] * W_SCALE;
    for (int i = tid; i < 512; i += 256) sWfc1[i] = Wfc1[i] * INV_SQRT8_C;
    __syncthreads();

    const int niter = N_EDGES / EPB;
    int li = 0;
    for (int it = blockIdx.x; it < niter; it += gridDim.x, ++li) {
        const int e0 = it * EPB;
        const int r = li & 1;

        if (tid < EPB) asm volatile("cp.async.bulk.wait_group 1;" ::: "memory");

        // phase A: h for EPB edges (512 values, 2 per thread)
#pragma unroll
        for (int i = tid; i < EPB * 64; i += 256) {
            const int el = i >> 6, k = i & 63;
            const int e = e0 + el;
            const float4 b0 = __ldg(reinterpret_cast<const float4*>(edge_basis + (size_t)e * 8));
            const float4 b1 = __ldg(reinterpret_cast<const float4*>(edge_basis + (size_t)e * 8) + 1);
            float acc;
            acc = b0.x * sWfc1[0 * 64 + k];
            acc = fmaf(b0.y, sWfc1[1 * 64 + k], acc);
            acc = fmaf(b0.z, sWfc1[2 * 64 + k], acc);
            acc = fmaf(b0.w, sWfc1[3 * 64 + k], acc);
            acc = fmaf(b1.x, sWfc1[4 * 64 + k], acc);
            acc = fmaf(b1.y, sWfc1[5 * 64 + k], acc);
            acc = fmaf(b1.z, sWfc1[6 * 64 + k], acc);
            acc = fmaf(b1.w, sWfc1[7 * 64 + k], acc);
            // ssp(x) = max(x,0) + log(1 + exp(-|x|)) - log(2)
            const float t = __expf(-fabsf(acc));
            sH[el][k] = fmaxf(acc, 0.f) + __logf(1.f + t) - LOG2_C;
        }
        if (tid < EPB) {
            const int e = e0 + tid;
            sSh[tid] = *reinterpret_cast<const float4*>(edge_sh + (size_t)e * 4);
            const int2 ij = *reinterpret_cast<const int2*>(edge_idx + (size_t)e * 2);
            sDst[tid] = ij.x;
            sSrc[tid] = ij.y;
        }
        __syncthreads();

        // phase B: w[col] for EPB edges (col = tid, Wfc2 column in registers)
        float wv[EPB];
#pragma unroll
        for (int q = 0; q < EPB; ++q) wv[q] = 0.f;
#pragma unroll
        for (int k4 = 0; k4 < 16; ++k4) {
#pragma unroll
            for (int q = 0; q < EPB; ++q) {
                const float4 h4 = ld4s(&sH[q][k4 * 4]);
                wv[q] = fmaf(h4.x, wcol[4 * k4 + 0], wv[q]);
                wv[q] = fmaf(h4.y, wcol[4 * k4 + 1], wv[q]);
                wv[q] = fmaf(h4.z, wcol[4 * k4 + 2], wv[q]);
                wv[q] = fmaf(h4.w, wcol[4 * k4 + 3], wv[q]);
            }
        }

        // phase C: gather + tensor product -> staging smem
#pragma unroll
        for (int q = 0; q < EPB; ++q) {
            const float w = wv[q];
            const float* nrow = d_sv + (size_t)sSrc[q] * 256;
            const float4 sh = sSh[q];
            float* st = sOut[r][q];
            const int col = tid;
            if (col < 64) {
                st[col] = w * nrow[col] * sh.x;
            } else if (col < 128) {
                const int u = col - 64;
                const float b = w * nrow[u];
                st[128 + 3 * u + 0] = b * sh.y;
                st[128 + 3 * u + 1] = b * sh.z;
                st[128 + 3 * u + 2] = b * sh.w;
            } else if (col < 192) {
                const int u = col - 128;
                const float ws = w * sh.x;
                st[320 + 3 * u + 0] = ws * nrow[64 + 3 * u + 0];
                st[320 + 3 * u + 1] = ws * nrow[64 + 3 * u + 1];
                st[320 + 3 * u + 2] = ws * nrow[64 + 3 * u + 2];
            } else {
                const int u = col - 192;
                const float x0 = nrow[64 + 3 * u + 0];
                const float x1 = nrow[64 + 3 * u + 1];
                const float x2 = nrow[64 + 3 * u + 2];
                st[64 + u] = w * INV_SQRT3_C * (x0 * sh.y + x1 * sh.z + x2 * sh.w);
            }
        }
        __syncthreads();

        if (tid < EPB) {
            asm volatile("fence.proxy.async.shared::cta;" ::: "memory");
            float* gdst = d_agg + (size_t)sDst[tid] * 512;
            const unsigned saddr = smem_u32(&sOut[r][tid][0]);
            asm volatile(
                "cp.reduce.async.bulk.global.shared::cta.bulk_group.add.f32 [%0], [%1], %2;"
                :: "l"(gdst), "r"(saddr), "n"(2048) : "memory");
            asm volatile("cp.async.bulk.commit_group;" ::: "memory");
        }
    }
    if (tid < EPB) asm volatile("cp.async.bulk.wait_group 0;" ::: "memory");
}

// ---------------------------------------------------------------------------
// out_s: unified 640-k GEMM. Weights k-major [640][64], scales folded.
// Warp -> 3 nodes (broadcast acts), lane -> col pair. 24 nodes/tile.
// smem: sW 40960 | sAct 24*640=15360  -> 56320 floats = 225280 B
// ---------------------------------------------------------------------------
__global__ void __launch_bounds__(256)
out_s_kernel(const float* __restrict__ node_feat,
             const float* __restrict__ node_attr,
             const float* __restrict__ W2s,
             const float* __restrict__ Wsc_s,
             float* __restrict__ out)
{
    extern __shared__ float sm[];
    float* sW   = sm;            // [640][64]
    float* sAct = sm + 40960;    // [24][640]
    const int tid = threadIdx.x;
    const int lane = tid & 31, wid = tid >> 5;

    for (int i = tid; i < 8192;  i += 256) sW[i]        = W2s[i]  * SC_A_C;
    for (int i = tid; i < 32768; i += 256) sW[8192 + i] = Wsc_s[i] * SC_B_C;
    __syncthreads();

    const int ngr = (N_NODES + 23) / 24;
    for (int g = blockIdx.x; g < ngr; g += gridDim.x) {
        const int n0 = g * 24;
        __syncthreads();
        for (int i = tid; i < 24 * 640; i += 256) {
            const int nl = i / 640;
            const int k  = i - nl * 640;
            const int n  = n0 + nl;
            float v = 0.f;
            if (n < N_NODES) {
                if (k < 128) v = d_agg[(size_t)n * 512 + k];
                else {
                    const int p = k - 128;
                    v = node_feat[(size_t)n * 256 + (p >> 3)] * node_attr[(size_t)n * 8 + (p & 7)];
                }
            }
            sAct[i] = v;
        }
        __syncthreads();

        const float* a0 = sAct + (wid * 3 + 0) * 640;
        const float* a1 = sAct + (wid * 3 + 1) * 640;
        const float* a2 = sAct + (wid * 3 + 2) * 640;
        const float* wp = sW + 2 * lane;

        float c00 = 0.f, c01 = 0.f, c10 = 0.f, c11 = 0.f, c20 = 0.f, c21 = 0.f;
#pragma unroll 4
        for (int k4 = 0; k4 < 160; ++k4) {
            const float4 x0 = ld4s(a0 + 4 * k4);
            const float4 x1 = ld4s(a1 + 4 * k4);
            const float4 x2 = ld4s(a2 + 4 * k4);
            const float2 w0 = ld2s(wp + (4 * k4 + 0) * 64);
            const float2 w1 = ld2s(wp + (4 * k4 + 1) * 64);
            const float2 w2 = ld2s(wp + (4 * k4 + 2) * 64);
            const float2 w3 = ld2s(wp + (4 * k4 + 3) * 64);
            c00 = fmaf(x0.x, w0.x, c00); c01 = fmaf(x0.x, w0.y, c01);
            c10 = fmaf(x1.x, w0.x, c10); c11 = fmaf(x1.x, w0.y, c11);
            c20 = fmaf(x2.x, w0.x, c20); c21 = fmaf(x2.x, w0.y, c21);
            c00 = fmaf(x0.y, w1.x, c00); c01 = fmaf(x0.y, w1.y, c01);
            c10 = fmaf(x1.y, w1.x, c10); c11 = fmaf(x1.y, w1.y, c11);
            c20 = fmaf(x2.y, w1.x, c20); c21 = fmaf(x2.y, w1.y, c21);
            c00 = fmaf(x0.z, w2.x, c00); c01 = fmaf(x0.z, w2.y, c01);
            c10 = fmaf(x1.z, w2.x, c10); c11 = fmaf(x1.z, w2.y, c11);
            c20 = fmaf(x2.z, w2.x, c20); c21 = fmaf(x2.z, w2.y, c21);
            c00 = fmaf(x0.w, w3.x, c00); c01 = fmaf(x0.w, w3.y, c01);
            c10 = fmaf(x1.w, w3.x, c10); c11 = fmaf(x1.w, w3.y, c11);
            c20 = fmaf(x2.w, w3.x, c20); c21 = fmaf(x2.w, w3.y, c21);
        }

        const int na = n0 + wid * 3;
        if (na + 0 < N_NODES) { out[(size_t)(na + 0) * 256 + 2 * lane] = c00; out[(size_t)(na + 0) * 256 + 2 * lane + 1] = c01; }
        if (na + 1 < N_NODES) { out[(size_t)(na + 1) * 256 + 2 * lane] = c10; out[(size_t)(na + 1) * 256 + 2 * lane + 1] = c11; }
        if (na + 2 < N_NODES) { out[(size_t)(na + 2) * 256 + 2 * lane] = c20; out[(size_t)(na + 2) * 256 + 2 * lane + 1] = c21; }
    }
}

// ---------------------------------------------------------------------------
// out_v: same GEMM core; warp -> 1 node, 3 component act-rows. 8 nodes/tile.
// smem: sW 40960 | sAct 8*3*640=15360
// ---------------------------------------------------------------------------
__global__ void __launch_bounds__(256)
out_v_kernel(const float* __restrict__ node_feat,
             const float* __restrict__ node_attr,
             const float* __restrict__ W2v,
             const float* __restrict__ Wsc_v,
             float* __restrict__ out)
{
    extern __shared__ float sm[];
    float* sW   = sm;            // [640][64]
    float* sAct = sm + 40960;    // [8][3][640]
    const int tid = threadIdx.x;
    const int lane = tid & 31, wid = tid >> 5;

    for (int i = tid; i < 8192;  i += 256) sW[i]        = W2v[i]  * SC_A_C;
    for (int i = tid; i < 32768; i += 256) sW[8192 + i] = Wsc_v[i] * SC_B_C;
    __syncthreads();

    const int ngr = N_NODES / 8;   // 2500, exact
    for (int g = blockIdx.x; g < ngr; g += gridDim.x) {
        const int n0 = g * 8;
        __syncthreads();
        for (int i = tid; i < 8 * 3 * 640; i += 256) {
            const int nl = i / 1920;
            const int r  = i - nl * 1920;
            const int c  = r / 640;
            const int k  = r - c * 640;
            const int n  = n0 + nl;
            float v;
            if (k < 128) v = d_agg[(size_t)n * 512 + 128 + 3 * k + c];
            else {
                const int p = k - 128;
                v = node_feat[(size_t)n * 256 + 64 + 3 * (p >> 3) + c] *
                    node_attr[(size_t)n * 8 + (p & 7)];
            }
            sAct[i] = v;
        }
        __syncthreads();

        const float* a0 = sAct + wid * 1920 + 0 * 640;
        const float* a1 = sAct + wid * 1920 + 1 * 640;
        const float* a2 = sAct + wid * 1920 + 2 * 640;
        const float* wp = sW + 2 * lane;

        float c00 = 0.f, c01 = 0.f, c10 = 0.f, c11 = 0.f, c20 = 0.f, c21 = 0.f;
#pragma unroll 4
        for (int k4 = 0; k4 < 160; ++k4) {
            const float4 x0 = ld4s(a0 + 4 * k4);
            const float4 x1 = ld4s(a1 + 4 * k4);
            const float4 x2 = ld4s(a2 + 4 * k4);
            const float2 w0 = ld2s(wp + (4 * k4 + 0) * 64);
            const float2 w1 = ld2s(wp + (4 * k4 + 1) * 64);
            const float2 w2 = ld2s(wp + (4 * k4 + 2) * 64);
            const float2 w3 = ld2s(wp + (4 * k4 + 3) * 64);
            c00 = fmaf(x0.x, w0.x, c00); c01 = fmaf(x0.x, w0.y, c01);
            c10 = fmaf(x1.x, w0.x, c10); c11 = fmaf(x1.x, w0.y, c11);
            c20 = fmaf(x2.x, w0.x, c20); c21 = fmaf(x2.x, w0.y, c21);
            c00 = fmaf(x0.y, w1.x, c00); c01 = fmaf(x0.y, w1.y, c01);
            c10 = fmaf(x1.y, w1.x, c10); c11 = fmaf(x1.y, w1.y, c11);
            c20 = fmaf(x2.y, w1.x, c20); c21 = fmaf(x2.y, w1.y, c21);
            c00 = fmaf(x0.z, w2.x, c00); c01 = fmaf(x0.z, w2.y, c01);
            c10 = fmaf(x1.z, w2.x, c10); c11 = fmaf(x1.z, w2.y, c11);
            c20 = fmaf(x2.z, w2.x, c20); c21 = fmaf(x2.z, w2.y, c21);
            c00 = fmaf(x0.w, w3.x, c00); c01 = fmaf(x0.w, w3.y, c01);
            c10 = fmaf(x1.w, w3.x, c10); c11 = fmaf(x1.w, w3.y, c11);
            c20 = fmaf(x2.w, w3.x, c20); c21 = fmaf(x2.w, w3.y, c21);
        }

        const int n = n0 + wid;
        float* o = out + (size_t)n * 256 + 64;
        const int col0 = 2 * lane, col1 = 2 * lane + 1;
        o[3 * col0 + 0] = c00; o[3 * col1 + 0] = c01;
        o[3 * col0 + 1] = c10; o[3 * col1 + 1] = c11;
        o[3 * col0 + 2] = c20; o[3 * col1 + 2] = c21;
    }
}

// ---------------------------------------------------------------------------
extern "C" void kernel_launch(void* const* d_in, const int* /*in_sizes*/, int /*n_in*/,
                              void* d_out, int /*out_size*/)
{
    const float* node_feat  = (const float*)d_in[0];
    const float* node_attr  = (const float*)d_in[1];
    const float* edge_sh    = (const float*)d_in[2];
    const float* edge_basis = (const float*)d_in[3];
    const float* W1s        = (const float*)d_in[4];
    const float* W1v        = (const float*)d_in[5];
    const float* Wfc1       = (const float*)d_in[6];
    const float* Wfc2       = (const float*)d_in[7];
    const float* W2s        = (const float*)d_in[8];
    const float* W2v        = (const float*)d_in[9];
    const float* Wsc_s      = (const float*)d_in[10];
    const float* Wsc_v      = (const float*)d_in[11];
    const int*   edge_idx   = (const int*)d_in[12];
    float* out = (float*)d_out;

    const int smem_bytes = 56320 * 4;   // 225280
    cudaFuncSetAttribute(out_s_kernel, cudaFuncAttributeMaxDynamicSharedMemorySize, smem_bytes);
    cudaFuncSetAttribute(out_v_kernel, cudaFuncAttributeMaxDynamicSharedMemorySize, smem_bytes);

    zero_agg_kernel<<<(N_NODES * 128 + 255) / 256, 256>>>();
    nodeprep_kernel<<<296, 256>>>(node_feat, W1s, W1v);
    edge_kernel<<<296, 256>>>(edge_sh, edge_basis, Wfc1, Wfc2, edge_idx);
    out_s_kernel<<<148, 256, smem_bytes>>>(node_feat, node_attr, W2s, Wsc_s, out);
    out_v_kernel<<<148, 256, smem_bytes>>>(node_feat, node_attr, W2v, Wsc_v, out);
}

// round 6
// speedup vs baseline: 1.2026x; 1.2026x over previous
#include <cuda_runtime.h>
#include <cstdint>
#include <cstddef>

#define N_NODES 20000
#define N_EDGES 320000
#define EPB 8

#define LOG2_C       0.6931471805599453f
#define INV_SQRT3_C  0.5773502691896258f
#define INV_SQRT8_C  0.35355339059327373f
#define W_SCALE      0.125f
#define INV_MUL_C    0.125f
#define SC_A_C       0.02209708691207961f   // 1/sqrt(128) * 1/sqrt(16)
#define SC_B_C       0.04419417382415922f   // 1/sqrt(512)

__device__ __align__(1024) float d_sv[(size_t)N_NODES * 256];
__device__ __align__(1024) float d_agg[(size_t)N_NODES * 512];

__device__ __forceinline__ unsigned smem_u32(const void* p) {
    return (unsigned)__cvta_generic_to_shared(p);
}
__device__ __forceinline__ float4 ld4s(const float* p) {
    return *reinterpret_cast<const float4*>(p);
}

// ---------------------------------------------------------------------------
__global__ void zero_agg_kernel() {
    size_t i = (size_t)blockIdx.x * blockDim.x + threadIdx.x;
    float4* p = reinterpret_cast<float4*>(d_agg);
    if (i < (size_t)N_NODES * 128) p[i] = make_float4(0.f, 0.f, 0.f, 0.f);
}

// ---------------------------------------------------------------------------
// node prep: s = s0 @ W1s ; v = v0 @ W1v, scaled 1/8
// ---------------------------------------------------------------------------
__global__ void __launch_bounds__(256)
nodeprep_kernel(const float* __restrict__ node_feat,
                const float* __restrict__ W1s,
                const float* __restrict__ W1v)
{
    __shared__ float sW1s[4096];
    __shared__ float sW1v[4096];
    __shared__ float sNF[4][256];

    const int tid = threadIdx.x;
    for (int i = tid; i < 4096; i += 256) { sW1s[i] = W1s[i]; sW1v[i] = W1v[i]; }
    __syncthreads();

    const int ngroups = (N_NODES + 3) / 4;
    for (int g = blockIdx.x; g < ngroups; g += gridDim.x) {
        const int n0 = g * 4;
        __syncthreads();
        for (int i = tid; i < 1024; i += 256) {
            const int nl = i >> 8, j = i & 255;
            const int n = n0 + nl;
            sNF[nl][j] = (n < N_NODES) ? node_feat[(size_t)n * 256 + j] : 0.f;
        }
        __syncthreads();
        const int nl = tid >> 6, w = tid & 63;
        const int n = n0 + nl;
        if (n < N_NODES) {
            float sacc = 0.f, v0a = 0.f, v1a = 0.f, v2a = 0.f;
#pragma unroll
            for (int u = 0; u < 64; ++u) {
                const float ws = sW1s[u * 64 + w];
                const float wv = sW1v[u * 64 + w];
                sacc = fmaf(sNF[nl][u], ws, sacc);
                v0a  = fmaf(sNF[nl][64 + 3 * u + 0], wv, v0a);
                v1a  = fmaf(sNF[nl][64 + 3 * u + 1], wv, v1a);
                v2a  = fmaf(sNF[nl][64 + 3 * u + 2], wv, v2a);
            }
            float* o = d_sv + (size_t)n * 256;
            o[w] = sacc * INV_MUL_C;
            o[64 + 3 * w + 0] = v0a * INV_MUL_C;
            o[64 + 3 * w + 1] = v1a * INV_MUL_C;
            o[64 + 3 * w + 2] = v2a * INV_MUL_C;
        }
    }
}

// ---------------------------------------------------------------------------
// edge kernel (unchanged from R5): fused FC1 -> ssp -> FC2 -> gather ->
// tensor product -> cp.reduce.async.bulk scatter, EPB=8.
// ---------------------------------------------------------------------------
__global__ void __launch_bounds__(256, 2)
edge_kernel(const float* __restrict__ edge_sh,
            const float* __restrict__ edge_basis,
            const float* __restrict__ Wfc1,
            const float* __restrict__ Wfc2,
            const int*   __restrict__ edge_idx)
{
    __shared__ float sWfc1[512];
    __shared__ __align__(16) float sH[EPB][64];
    __shared__ __align__(16) float sOut[2][EPB][512];
    __shared__ int    sSrc[EPB];
    __shared__ int    sDst[EPB];
    __shared__ float4 sSh[EPB];

    const int tid = threadIdx.x;

    float wcol[64];
#pragma unroll
    for (int k = 0; k < 64; ++k) wcol[k] = Wfc2[k * 256 + tid] * W_SCALE;
    for (int i = tid; i < 512; i += 256) sWfc1[i] = Wfc1[i] * INV_SQRT8_C;
    __syncthreads();

    const int niter = N_EDGES / EPB;
    int li = 0;
    for (int it = blockIdx.x; it < niter; it += gridDim.x, ++li) {
        const int e0 = it * EPB;
        const int r = li & 1;

        if (tid < EPB) asm volatile("cp.async.bulk.wait_group 1;" ::: "memory");

#pragma unroll
        for (int i = tid; i < EPB * 64; i += 256) {
            const int el = i >> 6, k = i & 63;
            const int e = e0 + el;
            const float4 b0 = __ldg(reinterpret_cast<const float4*>(edge_basis + (size_t)e * 8));
            const float4 b1 = __ldg(reinterpret_cast<const float4*>(edge_basis + (size_t)e * 8) + 1);
            float acc;
            acc = b0.x * sWfc1[0 * 64 + k];
            acc = fmaf(b0.y, sWfc1[1 * 64 + k], acc);
            acc = fmaf(b0.z, sWfc1[2 * 64 + k], acc);
            acc = fmaf(b0.w, sWfc1[3 * 64 + k], acc);
            acc = fmaf(b1.x, sWfc1[4 * 64 + k], acc);
            acc = fmaf(b1.y, sWfc1[5 * 64 + k], acc);
            acc = fmaf(b1.z, sWfc1[6 * 64 + k], acc);
            acc = fmaf(b1.w, sWfc1[7 * 64 + k], acc);
            const float t = __expf(-fabsf(acc));
            sH[el][k] = fmaxf(acc, 0.f) + __logf(1.f + t) - LOG2_C;
        }
        if (tid < EPB) {
            const int e = e0 + tid;
            sSh[tid] = *reinterpret_cast<const float4*>(edge_sh + (size_t)e * 4);
            const int2 ij = *reinterpret_cast<const int2*>(edge_idx + (size_t)e * 2);
            sDst[tid] = ij.x;
            sSrc[tid] = ij.y;
        }
        __syncthreads();

        float wv[EPB];
#pragma unroll
        for (int q = 0; q < EPB; ++q) wv[q] = 0.f;
#pragma unroll
        for (int k4 = 0; k4 < 16; ++k4) {
#pragma unroll
            for (int q = 0; q < EPB; ++q) {
                const float4 h4 = ld4s(&sH[q][k4 * 4]);
                wv[q] = fmaf(h4.x, wcol[4 * k4 + 0], wv[q]);
                wv[q] = fmaf(h4.y, wcol[4 * k4 + 1], wv[q]);
                wv[q] = fmaf(h4.z, wcol[4 * k4 + 2], wv[q]);
                wv[q] = fmaf(h4.w, wcol[4 * k4 + 3], wv[q]);
            }
        }

#pragma unroll
        for (int q = 0; q < EPB; ++q) {
            const float w = wv[q];
            const float* nrow = d_sv + (size_t)sSrc[q] * 256;
            const float4 sh = sSh[q];
            float* st = sOut[r][q];
            const int col = tid;
            if (col < 64) {
                st[col] = w * nrow[col] * sh.x;
            } else if (col < 128) {
                const int u = col - 64;
                const float b = w * nrow[u];
                st[128 + 3 * u + 0] = b * sh.y;
                st[128 + 3 * u + 1] = b * sh.z;
                st[128 + 3 * u + 2] = b * sh.w;
            } else if (col < 192) {
                const int u = col - 128;
                const float ws = w * sh.x;
                st[320 + 3 * u + 0] = ws * nrow[64 + 3 * u + 0];
                st[320 + 3 * u + 1] = ws * nrow[64 + 3 * u + 1];
                st[320 + 3 * u + 2] = ws * nrow[64 + 3 * u + 2];
            } else {
                const int u = col - 192;
                const float x0 = nrow[64 + 3 * u + 0];
                const float x1 = nrow[64 + 3 * u + 1];
                const float x2 = nrow[64 + 3 * u + 2];
                st[64 + u] = w * INV_SQRT3_C * (x0 * sh.y + x1 * sh.z + x2 * sh.w);
            }
        }
        __syncthreads();

        if (tid < EPB) {
            asm volatile("fence.proxy.async.shared::cta;" ::: "memory");
            float* gdst = d_agg + (size_t)sDst[tid] * 512;
            const unsigned saddr = smem_u32(&sOut[r][tid][0]);
            asm volatile(
                "cp.reduce.async.bulk.global.shared::cta.bulk_group.add.f32 [%0], [%1], %2;"
                :: "l"(gdst), "r"(saddr), "n"(2048) : "memory");
            asm volatile("cp.async.bulk.commit_group;" ::: "memory");
        }
    }
    if (tid < EPB) asm volatile("cp.async.bulk.wait_group 0;" ::: "memory");
}

// ===========================================================================
// Register-tiled SGEMM out kernels.
// CTA: 64 rows x 64 cols, K=640 in 4 chunks of 160.
// 256 threads = 16(ty) x 16(tx); thread computes 4x4 C tile.
// smem: sA [64][160] row-major (pitch 160), sB [160][64] k-major.
// Per 4-k: 4 broadcast LDS.128 (A) + 4 conflict-free LDS.128 (B) : 64 FMA.
// 80KB smem -> 2 CTAs/SM.
// ===========================================================================
#define KCHUNK 160
#define PA 160
#define PB 64
#define OUT_SMEM_FLOATS (64 * PA + KCHUNK * PB)   // 20480 floats = 81920 B

// mode 0: out_s rows = nodes; mode 1: out_v rows = 3*nodes (row = 3n+c)
template<int MODE>
__global__ void __launch_bounds__(256, 2)
out_gemm_kernel(const float* __restrict__ node_feat,
                const float* __restrict__ node_attr,
                const float* __restrict__ W2,
                const float* __restrict__ Wsc,
                float* __restrict__ out)
{
    extern __shared__ float sm[];
    float* sA = sm;              // [64][PA]
    float* sB = sm + 64 * PA;    // [KCHUNK][PB]

    const int tid  = threadIdx.x;
    const int tx   = tid & 15;        // col group
    const int ty   = tid >> 4;        // row group
    const int warp = tid >> 5, lane = tid & 31;

    const int r0 = blockIdx.x * 64;   // global row base
    const int MROWS = (MODE == 0) ? N_NODES : 3 * N_NODES;

    float acc[4][4];
#pragma unroll
    for (int i = 0; i < 4; ++i)
#pragma unroll
        for (int j = 0; j < 4; ++j) acc[i][j] = 0.f;

    for (int c = 0; c < 4; ++c) {
        const int k0 = c * KCHUNK;
        __syncthreads();
        // ---- stage A: warp per row, lanes along k (coalesced) ----
#pragma unroll
        for (int m = warp; m < 64; m += 8) {
            const int grow = r0 + m;
#pragma unroll
            for (int j = 0; j < KCHUNK / 32; ++j) {
                const int kk = lane + 32 * j;
                const int kg = k0 + kk;
                float v = 0.f;
                if (grow < MROWS) {
                    if (MODE == 0) {
                        const int n = grow;
                        if (kg < 128) v = d_agg[(size_t)n * 512 + kg];
                        else {
                            const int p = kg - 128;
                            v = node_feat[(size_t)n * 256 + (p >> 3)] *
                                node_attr[(size_t)n * 8 + (p & 7)];
                        }
                    } else {
                        const int n = grow / 3, cc = grow - 3 * (grow / 3);
                        if (kg < 128) v = d_agg[(size_t)n * 512 + 128 + 3 * kg + cc];
                        else {
                            const int p = kg - 128;
                            v = node_feat[(size_t)n * 256 + 64 + 3 * (p >> 3) + cc] *
                                node_attr[(size_t)n * 8 + (p & 7)];
                        }
                    }
                }
                sA[m * PA + kk] = v;
            }
        }
        // ---- stage B: weights k-major, scales folded ----
        for (int i = tid; i < KCHUNK * 64; i += 256) {
            const int kk = i >> 6, nn = i & 63;
            const int kg = k0 + kk;
            const float v = (kg < 128) ? W2[kg * 64 + nn] * SC_A_C
                                       : Wsc[(kg - 128) * 64 + nn] * SC_B_C;
            sB[kk * PB + nn] = v;
        }
        __syncthreads();

        // ---- compute ----
        const float* pa = sA + (4 * ty) * PA;
        const float* pb = sB + 4 * tx;
#pragma unroll 4
        for (int k4 = 0; k4 < KCHUNK / 4; ++k4) {
            const float4 a0 = ld4s(pa + 0 * PA + 4 * k4);
            const float4 a1 = ld4s(pa + 1 * PA + 4 * k4);
            const float4 a2 = ld4s(pa + 2 * PA + 4 * k4);
            const float4 a3 = ld4s(pa + 3 * PA + 4 * k4);
            const float4 b0 = ld4s(pb + (4 * k4 + 0) * PB);
            const float4 b1 = ld4s(pb + (4 * k4 + 1) * PB);
            const float4 b2 = ld4s(pb + (4 * k4 + 2) * PB);
            const float4 b3 = ld4s(pb + (4 * k4 + 3) * PB);

            acc[0][0] = fmaf(a0.x, b0.x, acc[0][0]); acc[0][1] = fmaf(a0.x, b0.y, acc[0][1]);
            acc[0][2] = fmaf(a0.x, b0.z, acc[0][2]); acc[0][3] = fmaf(a0.x, b0.w, acc[0][3]);
            acc[1][0] = fmaf(a1.x, b0.x, acc[1][0]); acc[1][1] = fmaf(a1.x, b0.y, acc[1][1]);
            acc[1][2] = fmaf(a1.x, b0.z, acc[1][2]); acc[1][3] = fmaf(a1.x, b0.w, acc[1][3]);
            acc[2][0] = fmaf(a2.x, b0.x, acc[2][0]); acc[2][1] = fmaf(a2.x, b0.y, acc[2][1]);
            acc[2][2] = fmaf(a2.x, b0.z, acc[2][2]); acc[2][3] = fmaf(a2.x, b0.w, acc[2][3]);
            acc[3][0] = fmaf(a3.x, b0.x, acc[3][0]); acc[3][1] = fmaf(a3.x, b0.y, acc[3][1]);
            acc[3][2] = fmaf(a3.x, b0.z, acc[3][2]); acc[3][3] = fmaf(a3.x, b0.w, acc[3][3]);

            acc[0][0] = fmaf(a0.y, b1.x, acc[0][0]); acc[0][1] = fmaf(a0.y, b1.y, acc[0][1]);
            acc[0][2] = fmaf(a0.y, b1.z, acc[0][2]); acc[0][3] = fmaf(a0.y, b1.w, acc[0][3]);
            acc[1][0] = fmaf(a1.y, b1.x, acc[1][0]); acc[1][1] = fmaf(a1.y, b1.y, acc[1][1]);
            acc[1][2] = fmaf(a1.y, b1.z, acc[1][2]); acc[1][3] = fmaf(a1.y, b1.w, acc[1][3]);
            acc[2][0] = fmaf(a2.y, b1.x, acc[2][0]); acc[2][1] = fmaf(a2.y, b1.y, acc[2][1]);
            acc[2][2] = fmaf(a2.y, b1.z, acc[2][2]); acc[2][3] = fmaf(a2.y, b1.w, acc[2][3]);
            acc[3][0] = fmaf(a3.y, b1.x, acc[3][0]); acc[3][1] = fmaf(a3.y, b1.y, acc[3][1]);
            acc[3][2] = fmaf(a3.y, b1.z, acc[3][2]); acc[3][3] = fmaf(a3.y, b1.w, acc[3][3]);

            acc[0][0] = fmaf(a0.z, b2.x, acc[0][0]); acc[0][1] = fmaf(a0.z, b2.y, acc[0][1]);
            acc[0][2] = fmaf(a0.z, b2.z, acc[0][2]); acc[0][3] = fmaf(a0.z, b2.w, acc[0][3]);
            acc[1][0] = fmaf(a1.z, b2.x, acc[1][0]); acc[1][1] = fmaf(a1.z, b2.y, acc[1][1]);
            acc[1][2] = fmaf(a1.z, b2.z, acc[1][2]); acc[1][3] = fmaf(a1.z, b2.w, acc[1][3]);
            acc[2][0] = fmaf(a2.z, b2.x, acc[2][0]); acc[2][1] = fmaf(a2.z, b2.y, acc[2][1]);
            acc[2][2] = fmaf(a2.z, b2.z, acc[2][2]); acc[2][3] = fmaf(a2.z, b2.w, acc[2][3]);
            acc[3][0] = fmaf(a3.z, b2.x, acc[3][0]); acc[3][1] = fmaf(a3.z, b2.y, acc[3][1]);
            acc[3][2] = fmaf(a3.z, b2.z, acc[3][2]); acc[3][3] = fmaf(a3.z, b2.w, acc[3][3]);

            acc[0][0] = fmaf(a0.w, b3.x, acc[0][0]); acc[0][1] = fmaf(a0.w, b3.y, acc[0][1]);
            acc[0][2] = fmaf(a0.w, b3.z, acc[0][2]); acc[0][3] = fmaf(a0.w, b3.w, acc[0][3]);
            acc[1][0] = fmaf(a1.w, b3.x, acc[1][0]); acc[1][1] = fmaf(a1.w, b3.y, acc[1][1]);
            acc[1][2] = fmaf(a1.w, b3.z, acc[1][2]); acc[1][3] = fmaf(a1.w, b3.w, acc[1][3]);
            acc[2][0] = fmaf(a2.w, b3.x, acc[2][0]); acc[2][1] = fmaf(a2.w, b3.y, acc[2][1]);
            acc[2][2] = fmaf(a2.w, b3.z, acc[2][2]); acc[2][3] = fmaf(a2.w, b3.w, acc[2][3]);
            acc[3][0] = fmaf(a3.w, b3.x, acc[3][0]); acc[3][1] = fmaf(a3.w, b3.y, acc[3][1]);
            acc[3][2] = fmaf(a3.w, b3.z, acc[3][2]); acc[3][3] = fmaf(a3.w, b3.w, acc[3][3]);
        }
    }

    // ---- write C ----
#pragma unroll
    for (int r = 0; r < 4; ++r) {
        const int grow = r0 + 4 * ty + r;
        if (grow >= MROWS) continue;
        if (MODE == 0) {
            float4 v = make_float4(acc[r][0], acc[r][1], acc[r][2], acc[r][3]);
            *reinterpret_cast<float4*>(out + (size_t)grow * 256 + 4 * tx) = v;
        } else {
            const int n = grow / 3, cc = grow - 3 * (grow / 3);
            float* o = out + (size_t)n * 256 + 64 + cc;
#pragma unroll
            for (int j = 0; j < 4; ++j) o[3 * (4 * tx + j)] = acc[r][j];
        }
    }
}

// ---------------------------------------------------------------------------
extern "C" void kernel_launch(void* const* d_in, const int* /*in_sizes*/, int /*n_in*/,
                              void* d_out, int /*out_size*/)
{
    const float* node_feat  = (const float*)d_in[0];
    const float* node_attr  = (const float*)d_in[1];
    const float* edge_sh    = (const float*)d_in[2];
    const float* edge_basis = (const float*)d_in[3];
    const float* W1s        = (const float*)d_in[4];
    const float* W1v        = (const float*)d_in[5];
    const float* Wfc1       = (const float*)d_in[6];
    const float* Wfc2       = (const float*)d_in[7];
    const float* W2s        = (const float*)d_in[8];
    const float* W2v        = (const float*)d_in[9];
    const float* Wsc_s      = (const float*)d_in[10];
    const float* Wsc_v      = (const float*)d_in[11];
    const int*   edge_idx   = (const int*)d_in[12];
    float* out = (float*)d_out;

    const int smem_bytes = OUT_SMEM_FLOATS * 4;   // 81920
    cudaFuncSetAttribute(out_gemm_kernel<0>, cudaFuncAttributeMaxDynamicSharedMemorySize, smem_bytes);
    cudaFuncSetAttribute(out_gemm_kernel<1>, cudaFuncAttributeMaxDynamicSharedMemorySize, smem_bytes);

    zero_agg_kernel<<<(N_NODES * 128 + 255) / 256, 256>>>();
    nodeprep_kernel<<<296, 256>>>(node_feat, W1s, W1v);
    edge_kernel<<<296, 256>>>(edge_sh, edge_basis, Wfc1, Wfc2, edge_idx);

    const int tiles_s = (N_NODES + 63) / 64;          // 313
    const int tiles_v = (3 * N_NODES + 63) / 64;      // 938
    out_gemm_kernel<0><<<tiles_s, 256, smem_bytes>>>(node_feat, node_attr, W2s, Wsc_s, out);
    out_gemm_kernel<1><<<tiles_v, 256, smem_bytes>>>(node_feat, node_attr, W2v, Wsc_v, out);
}

// round 8
// speedup vs baseline: 1.2941x; 1.0760x over previous
#include <cuda_runtime.h>
#include <cstdint>
#include <cstddef>

#define N_NODES 20000
#define N_EDGES 320000
#define EPB 8

#define LOG2_C       0.6931471805599453f
#define INV_SQRT3_C  0.5773502691896258f
#define INV_SQRT8_C  0.35355339059327373f
#define W_SCALE      0.125f
#define INV_MUL_C    0.125f
#define SC_A_C       0.02209708691207961f   // 1/sqrt(128) * 1/sqrt(16)
#define SC_B_C       0.04419417382415922f   // 1/sqrt(512)

#define ROWS_S 20032                         // 313 * 64
#define ROWS_V 60032                         // 938 * 64

// scratch (__device__ globals: allocation-free rule).
// NOTE: referenced ONLY from device code — host-side references to __device__
// symbols yield the host shadow address (silently "works" via ATS on GB300,
// reading host zeros — the R7 bug).
__device__ __align__(1024) float d_sv[(size_t)N_NODES * 256];
__device__ __align__(1024) float d_cat_s[(size_t)ROWS_S * 640];
__device__ __align__(1024) float d_cat_v[(size_t)ROWS_V * 640];
__device__ __align__(1024) float d_Wcat_s[640 * 64];
__device__ __align__(1024) float d_Wcat_v[640 * 64];

__device__ __forceinline__ unsigned smem_u32(const void* p) {
    return (unsigned)__cvta_generic_to_shared(p);
}
__device__ __forceinline__ float4 ld4s(const float* p) {
    return *reinterpret_cast<const float4*>(p);
}
__device__ __forceinline__ void cp_async16(unsigned saddr, const float* gaddr) {
    asm volatile("cp.async.cg.shared.global [%0], [%1], 16;" :: "r"(saddr), "l"(gaddr));
}
__device__ __forceinline__ void cp_commit() {
    asm volatile("cp.async.commit_group;" ::: "memory");
}
template<int NWAIT>
__device__ __forceinline__ void cp_wait() {
    asm volatile("cp.async.wait_group %0;" :: "n"(NWAIT) : "memory");
}

// ---------------------------------------------------------------------------
// fold output scales into Wcat[640][64] for both branches
// ---------------------------------------------------------------------------
__global__ void wfold_kernel(const float* __restrict__ W2s, const float* __restrict__ Wsc_s,
                             const float* __restrict__ W2v, const float* __restrict__ Wsc_v)
{
    const int i = blockIdx.x * blockDim.x + threadIdx.x;
    if (i < 8192) {
        d_Wcat_s[i] = W2s[i] * SC_A_C;
        d_Wcat_v[i] = W2v[i] * SC_A_C;
    } else if (i < 40960) {
        d_Wcat_s[i] = Wsc_s[i - 8192] * SC_B_C;
        d_Wcat_v[i] = Wsc_v[i - 8192] * SC_B_C;
    }
}

// ---------------------------------------------------------------------------
// node prep: d_sv = [s0@W1s | v0@W1v] * 1/8  (for edge gather)
//            cat_s[n]    = [zeros(128) | s0 (x) attr (512)]
//            cat_v[3n+c] = [zeros(128) | v0[:,c] (x) attr (512)]
// ---------------------------------------------------------------------------
__global__ void __launch_bounds__(256)
nodeprep_kernel(const float* __restrict__ node_feat,
                const float* __restrict__ node_attr,
                const float* __restrict__ W1s,
                const float* __restrict__ W1v)
{
    __shared__ float sW1s[4096];
    __shared__ float sW1v[4096];
    __shared__ float sNF[4][256];
    __shared__ float4 sAT[4][2];

    const int tid = threadIdx.x;
    for (int i = tid; i < 4096; i += 256) { sW1s[i] = W1s[i]; sW1v[i] = W1v[i]; }
    __syncthreads();

    const int ngroups = N_NODES / 4;   // 5000 exact
    for (int g = blockIdx.x; g < ngroups; g += gridDim.x) {
        const int n0 = g * 4;
        __syncthreads();
        for (int i = tid; i < 1024; i += 256) {
            const int nl = i >> 8, j = i & 255;
            sNF[nl][j] = node_feat[(size_t)(n0 + nl) * 256 + j];
        }
        if (tid < 8) {
            const int nl = tid >> 1, j = tid & 1;
            sAT[nl][j] = __ldg(reinterpret_cast<const float4*>(node_attr + (size_t)(n0 + nl) * 8) + j);
        }
        __syncthreads();

        // ---- d_sv ----
        {
            const int nl = tid >> 6, w = tid & 63;
            const int n = n0 + nl;
            float sacc = 0.f, v0a = 0.f, v1a = 0.f, v2a = 0.f;
#pragma unroll
            for (int u = 0; u < 64; ++u) {
                const float ws = sW1s[u * 64 + w];
                const float wv = sW1v[u * 64 + w];
                sacc = fmaf(sNF[nl][u], ws, sacc);
                v0a  = fmaf(sNF[nl][64 + 3 * u + 0], wv, v0a);
                v1a  = fmaf(sNF[nl][64 + 3 * u + 1], wv, v1a);
                v2a  = fmaf(sNF[nl][64 + 3 * u + 2], wv, v2a);
            }
            float* o = d_sv + (size_t)n * 256;
            o[w] = sacc * INV_MUL_C;
            o[64 + 3 * w + 0] = v0a * INV_MUL_C;
            o[64 + 3 * w + 1] = v1a * INV_MUL_C;
            o[64 + 3 * w + 2] = v2a * INV_MUL_C;
        }

        // ---- zero agg regions (float4) ----
        if (tid < 128) {
            const int nl = tid >> 5, u = tid & 31;
            reinterpret_cast<float4*>(d_cat_s + (size_t)(n0 + nl) * 640)[u] =
                make_float4(0.f, 0.f, 0.f, 0.f);
        }
        for (int i = tid; i < 384; i += 256) {
            const int rr = i >> 5, u = i & 31;
            const int nl = rr / 3, c = rr - 3 * nl;
            reinterpret_cast<float4*>(d_cat_v + ((size_t)(n0 + nl) * 3 + c) * 640)[u] =
                make_float4(0.f, 0.f, 0.f, 0.f);
        }

        // ---- T_s ----
        for (int i = tid; i < 512; i += 256) {
            const int nl = i >> 7, p4 = i & 127;
            const float a = sNF[nl][p4 >> 1];
            const float4 at = sAT[nl][p4 & 1];
            reinterpret_cast<float4*>(d_cat_s + (size_t)(n0 + nl) * 640 + 128)[p4] =
                make_float4(a * at.x, a * at.y, a * at.z, a * at.w);
        }
        // ---- T_v ----
        for (int i = tid; i < 1536; i += 256) {
            const int nl = i / 384;
            const int r  = i - nl * 384;
            const int c  = r >> 7, p4 = r & 127;
            const float a = sNF[nl][64 + 3 * (p4 >> 1) + c];
            const float4 at = sAT[nl][p4 & 1];
            reinterpret_cast<float4*>(d_cat_v + ((size_t)(n0 + nl) * 3 + c) * 640 + 128)[p4] =
                make_float4(a * at.x, a * at.y, a * at.z, a * at.w);
        }
    }
}

// ---------------------------------------------------------------------------
// edge kernel: fused FC1 -> ssp -> FC2 -> gather -> tensor product ->
// 4x 512B cp.reduce.async.bulk per edge into cat_s / cat_v rows.
// ---------------------------------------------------------------------------
__global__ void __launch_bounds__(256, 2)
edge_kernel(const float* __restrict__ edge_sh,
            const float* __restrict__ edge_basis,
            const float* __restrict__ Wfc1,
            const float* __restrict__ Wfc2,
            const int*   __restrict__ edge_idx)
{
    __shared__ float sWfc1[512];
    __shared__ __align__(16) float sH[EPB][64];
    __shared__ __align__(16) float sOut[2][EPB][512];
    __shared__ int    sSrc[EPB];
    __shared__ int    sDst[EPB];
    __shared__ float4 sSh[EPB];

    const int tid = threadIdx.x;

    float wcol[64];
#pragma unroll
    for (int k = 0; k < 64; ++k) wcol[k] = Wfc2[k * 256 + tid] * W_SCALE;
    for (int i = tid; i < 512; i += 256) sWfc1[i] = Wfc1[i] * INV_SQRT8_C;
    __syncthreads();

    const int niter = N_EDGES / EPB;
    int li = 0;
    for (int it = blockIdx.x; it < niter; it += gridDim.x, ++li) {
        const int e0 = it * EPB;
        const int r = li & 1;

        // BULK family wait (guards sOut slot reuse vs in-flight bulk reduces)
        if (tid < 4 * EPB) asm volatile("cp.async.bulk.wait_group 1;" ::: "memory");

#pragma unroll
        for (int i = tid; i < EPB * 64; i += 256) {
            const int el = i >> 6, k = i & 63;
            const int e = e0 + el;
            const float4 b0 = __ldg(reinterpret_cast<const float4*>(edge_basis + (size_t)e * 8));
            const float4 b1 = __ldg(reinterpret_cast<const float4*>(edge_basis + (size_t)e * 8) + 1);
            float acc;
            acc = b0.x * sWfc1[0 * 64 + k];
            acc = fmaf(b0.y, sWfc1[1 * 64 + k], acc);
            acc = fmaf(b0.z, sWfc1[2 * 64 + k], acc);
            acc = fmaf(b0.w, sWfc1[3 * 64 + k], acc);
            acc = fmaf(b1.x, sWfc1[4 * 64 + k], acc);
            acc = fmaf(b1.y, sWfc1[5 * 64 + k], acc);
            acc = fmaf(b1.z, sWfc1[6 * 64 + k], acc);
            acc = fmaf(b1.w, sWfc1[7 * 64 + k], acc);
            const float t = __expf(-fabsf(acc));
            sH[el][k] = fmaxf(acc, 0.f) + __logf(1.f + t) - LOG2_C;
        }
        if (tid < EPB) {
            const int e = e0 + tid;
            sSh[tid] = *reinterpret_cast<const float4*>(edge_sh + (size_t)e * 4);
            const int2 ij = *reinterpret_cast<const int2*>(edge_idx + (size_t)e * 2);
            sDst[tid] = ij.x;
            sSrc[tid] = ij.y;
        }
        __syncthreads();

        float wv[EPB];
#pragma unroll
        for (int q = 0; q < EPB; ++q) wv[q] = 0.f;
#pragma unroll
        for (int k4 = 0; k4 < 16; ++k4) {
#pragma unroll
            for (int q = 0; q < EPB; ++q) {
                const float4 h4 = ld4s(&sH[q][k4 * 4]);
                wv[q] = fmaf(h4.x, wcol[4 * k4 + 0], wv[q]);
                wv[q] = fmaf(h4.y, wcol[4 * k4 + 1], wv[q]);
                wv[q] = fmaf(h4.z, wcol[4 * k4 + 2], wv[q]);
                wv[q] = fmaf(h4.w, wcol[4 * k4 + 3], wv[q]);
            }
        }

#pragma unroll
        for (int q = 0; q < EPB; ++q) {
            const float w = wv[q];
            const float* nrow = d_sv + (size_t)sSrc[q] * 256;
            const float4 sh = sSh[q];
            float* st = sOut[r][q];
            const int col = tid;
            if (col < 64) {                       // outA -> cat_s agg[0:64]
                st[col] = w * nrow[col] * sh.x;
            } else if (col < 128) {               // outB: m = u, c-major
                const int u = col - 64;
                const float b = w * nrow[u];
                st[128 + 0 * 128 + u] = b * sh.y;
                st[128 + 1 * 128 + u] = b * sh.z;
                st[128 + 2 * 128 + u] = b * sh.w;
            } else if (col < 192) {               // outC: m = 64+u, c-major
                const int u = col - 128;
                const float ws = w * sh.x;
                st[128 + 0 * 128 + 64 + u] = ws * nrow[64 + 3 * u + 0];
                st[128 + 1 * 128 + 64 + u] = ws * nrow[64 + 3 * u + 1];
                st[128 + 2 * 128 + 64 + u] = ws * nrow[64 + 3 * u + 2];
            } else {                              // outD -> cat_s agg[64:128]
                const int u = col - 192;
                const float x0 = nrow[64 + 3 * u + 0];
                const float x1 = nrow[64 + 3 * u + 1];
                const float x2 = nrow[64 + 3 * u + 2];
                st[64 + u] = w * INV_SQRT3_C * (x0 * sh.y + x1 * sh.z + x2 * sh.w);
            }
        }
        __syncthreads();

        if (tid < 4 * EPB) {
            asm volatile("fence.proxy.async.shared::cta;" ::: "memory");
            const int q = tid >> 2, part = tid & 3;
            const int dst = sDst[q];
            float* g = (part == 0)
                     ? (d_cat_s + (size_t)dst * 640)
                     : (d_cat_v + ((size_t)dst * 3 + (part - 1)) * 640);
            const unsigned saddr = smem_u32(&sOut[r][q][part * 128]);
            asm volatile(
                "cp.reduce.async.bulk.global.shared::cta.bulk_group.add.f32 [%0], [%1], %2;"
                :: "l"(g), "r"(saddr), "n"(512) : "memory");
            asm volatile("cp.async.bulk.commit_group;" ::: "memory");
        }
    }
    if (tid < 4 * EPB) asm volatile("cp.async.bulk.wait_group 0;" ::: "memory");
}

// ===========================================================================
// Pipelined register-tiled SGEMM: C[64 x 64] = A[rows][640] @ B[640][64]
// KCH=80, double-buffered cp.async. A/B resolved from device globals INSIDE
// the kernel (device-side symbol references — correct device addresses).
// ===========================================================================
#define KCH 80
#define PA 84
#define GEMM_SMEM ((2 * 64 * PA + 2 * KCH * 64) * 4)

template<int MODE>
__global__ void __launch_bounds__(256, 2)
out_gemm_kernel(float* __restrict__ out)
{
    const float* __restrict__ A = (MODE == 0) ? d_cat_s  : d_cat_v;
    const float* __restrict__ B = (MODE == 0) ? d_Wcat_s : d_Wcat_v;

    extern __shared__ float sm[];
    float* sA = sm;                    // [2][64*PA]
    float* sB = sm + 2 * 64 * PA;      // [2][KCH*64]

    const int tid = threadIdx.x;
    const int tx = tid & 15, ty = tid >> 4;
    const int r0 = blockIdx.x * 64;

    float acc[4][4];
#pragma unroll
    for (int i = 0; i < 4; ++i)
#pragma unroll
        for (int j = 0; j < 4; ++j) acc[i][j] = 0.f;

    auto stage = [&](int buf, int c) {
        const int k0 = c * KCH;
        float* sAb = sA + buf * 64 * PA;
        float* sBb = sB + buf * KCH * 64;
#pragma unroll
        for (int j = 0; j < 5; ++j) {          // A: 1280 x 16B
            const int idx = tid + 256 * j;
            const int row = idx / 20, u = idx - row * 20;
            cp_async16(smem_u32(sAb + row * PA + 4 * u),
                       A + (size_t)(r0 + row) * 640 + k0 + 4 * u);
        }
#pragma unroll
        for (int j = 0; j < 5; ++j) {          // B: 1280 x 16B
            const int idx = tid + 256 * j;
            const int row = idx >> 4, u = idx & 15;
            cp_async16(smem_u32(sBb + row * 64 + 4 * u),
                       B + (size_t)(k0 + row) * 64 + 4 * u);
        }
        cp_commit();
    };

    stage(0, 0);

#pragma unroll 1
    for (int c = 0; c < 8; ++c) {
        if (c < 7) { stage((c + 1) & 1, c + 1); cp_wait<1>(); }
        else       { cp_wait<0>(); }
        __syncthreads();

        const float* pa = sA + (c & 1) * 64 * PA + (4 * ty) * PA;
        const float* pb = sB + (c & 1) * KCH * 64 + 4 * tx;
#pragma unroll 4
        for (int k4 = 0; k4 < KCH / 4; ++k4) {
            const float4 a0 = ld4s(pa + 0 * PA + 4 * k4);
            const float4 a1 = ld4s(pa + 1 * PA + 4 * k4);
            const float4 a2 = ld4s(pa + 2 * PA + 4 * k4);
            const float4 a3 = ld4s(pa + 3 * PA + 4 * k4);
            const float4 b0 = ld4s(pb + (4 * k4 + 0) * 64);
            const float4 b1 = ld4s(pb + (4 * k4 + 1) * 64);
            const float4 b2 = ld4s(pb + (4 * k4 + 2) * 64);
            const float4 b3 = ld4s(pb + (4 * k4 + 3) * 64);

            acc[0][0] = fmaf(a0.x, b0.x, acc[0][0]); acc[0][1] = fmaf(a0.x, b0.y, acc[0][1]);
            acc[0][2] = fmaf(a0.x, b0.z, acc[0][2]); acc[0][3] = fmaf(a0.x, b0.w, acc[0][3]);
            acc[1][0] = fmaf(a1.x, b0.x, acc[1][0]); acc[1][1] = fmaf(a1.x, b0.y, acc[1][1]);
            acc[1][2] = fmaf(a1.x, b0.z, acc[1][2]); acc[1][3] = fmaf(a1.x, b0.w, acc[1][3]);
            acc[2][0] = fmaf(a2.x, b0.x, acc[2][0]); acc[2][1] = fmaf(a2.x, b0.y, acc[2][1]);
            acc[2][2] = fmaf(a2.x, b0.z, acc[2][2]); acc[2][3] = fmaf(a2.x, b0.w, acc[2][3]);
            acc[3][0] = fmaf(a3.x, b0.x, acc[3][0]); acc[3][1] = fmaf(a3.x, b0.y, acc[3][1]);
            acc[3][2] = fmaf(a3.x, b0.z, acc[3][2]); acc[3][3] = fmaf(a3.x, b0.w, acc[3][3]);

            acc[0][0] = fmaf(a0.y, b1.x, acc[0][0]); acc[0][1] = fmaf(a0.y, b1.y, acc[0][1]);
            acc[0][2] = fmaf(a0.y, b1.z, acc[0][2]); acc[0][3] = fmaf(a0.y, b1.w, acc[0][3]);
            acc[1][0] = fmaf(a1.y, b1.x, acc[1][0]); acc[1][1] = fmaf(a1.y, b1.y, acc[1][1]);
            acc[1][2] = fmaf(a1.y, b1.z, acc[1][2]); acc[1][3] = fmaf(a1.y, b1.w, acc[1][3]);
            acc[2][0] = fmaf(a2.y, b1.x, acc[2][0]); acc[2][1] = fmaf(a2.y, b1.y, acc[2][1]);
            acc[2][2] = fmaf(a2.y, b1.z, acc[2][2]); acc[2][3] = fmaf(a2.y, b1.w, acc[2][3]);
            acc[3][0] = fmaf(a3.y, b1.x, acc[3][0]); acc[3][1] = fmaf(a3.y, b1.y, acc[3][1]);
            acc[3][2] = fmaf(a3.y, b1.z, acc[3][2]); acc[3][3] = fmaf(a3.y, b1.w, acc[3][3]);

            acc[0][0] = fmaf(a0.z, b2.x, acc[0][0]); acc[0][1] = fmaf(a0.z, b2.y, acc[0][1]);
            acc[0][2] = fmaf(a0.z, b2.z, acc[0][2]); acc[0][3] = fmaf(a0.z, b2.w, acc[0][3]);
            acc[1][0] = fmaf(a1.z, b2.x, acc[1][0]); acc[1][1] = fmaf(a1.z, b2.y, acc[1][1]);
            acc[1][2] = fmaf(a1.z, b2.z, acc[1][2]); acc[1][3] = fmaf(a1.z, b2.w, acc[1][3]);
            acc[2][0] = fmaf(a2.z, b2.x, acc[2][0]); acc[2][1] = fmaf(a2.z, b2.y, acc[2][1]);
            acc[2][2] = fmaf(a2.z, b2.z, acc[2][2]); acc[2][3] = fmaf(a2.z, b2.w, acc[2][3]);
            acc[3][0] = fmaf(a3.z, b2.x, acc[3][0]); acc[3][1] = fmaf(a3.z, b2.y, acc[3][1]);
            acc[3][2] = fmaf(a3.z, b2.z, acc[3][2]); acc[3][3] = fmaf(a3.z, b2.w, acc[3][3]);

            acc[0][0] = fmaf(a0.w, b3.x, acc[0][0]); acc[0][1] = fmaf(a0.w, b3.y, acc[0][1]);
            acc[0][2] = fmaf(a0.w, b3.z, acc[0][2]); acc[0][3] = fmaf(a0.w, b3.w, acc[0][3]);
            acc[1][0] = fmaf(a1.w, b3.x, acc[1][0]); acc[1][1] = fmaf(a1.w, b3.y, acc[1][1]);
            acc[1][2] = fmaf(a1.w, b3.z, acc[1][2]); acc[1][3] = fmaf(a1.w, b3.w, acc[1][3]);
            acc[2][0] = fmaf(a2.w, b3.x, acc[2][0]); acc[2][1] = fmaf(a2.w, b3.y, acc[2][1]);
            acc[2][2] = fmaf(a2.w, b3.z, acc[2][2]); acc[2][3] = fmaf(a2.w, b3.w, acc[2][3]);
            acc[3][0] = fmaf(a3.w, b3.x, acc[3][0]); acc[3][1] = fmaf(a3.w, b3.y, acc[3][1]);
            acc[3][2] = fmaf(a3.w, b3.z, acc[3][2]); acc[3][3] = fmaf(a3.w, b3.w, acc[3][3]);
        }
        __syncthreads();
    }

#pragma unroll
    for (int r = 0; r < 4; ++r) {
        const int grow = r0 + 4 * ty + r;
        if (MODE == 0) {
            if (grow < N_NODES) {
                float4 v = make_float4(acc[r][0], acc[r][1], acc[r][2], acc[r][3]);
                *reinterpret_cast<float4*>(out + (size_t)grow * 256 + 4 * tx) = v;
            }
        } else {
            if (grow < 3 * N_NODES) {
                const int n = grow / 3, cc = grow - 3 * (grow / 3);
                float* o = out + (size_t)n * 256 + 64 + cc;
#pragma unroll
                for (int j = 0; j < 4; ++j) o[3 * (4 * tx + j)] = acc[r][j];
            }
        }
    }
}

// ---------------------------------------------------------------------------
extern "C" void kernel_launch(void* const* d_in, const int* /*in_sizes*/, int /*n_in*/,
                              void* d_out, int /*out_size*/)
{
    const float* node_feat  = (const float*)d_in[0];
    const float* node_attr  = (const float*)d_in[1];
    const float* edge_sh    = (const float*)d_in[2];
    const float* edge_basis = (const float*)d_in[3];
    const float* W1s        = (const float*)d_in[4];
    const float* W1v        = (const float*)d_in[5];
    const float* Wfc1       = (const float*)d_in[6];
    const float* Wfc2       = (const float*)d_in[7];
    const float* W2s        = (const float*)d_in[8];
    const float* W2v        = (const float*)d_in[9];
    const float* Wsc_s      = (const float*)d_in[10];
    const float* Wsc_v      = (const float*)d_in[11];
    const int*   edge_idx   = (const int*)d_in[12];
    float* out = (float*)d_out;

    cudaFuncSetAttribute(out_gemm_kernel<0>, cudaFuncAttributeMaxDynamicSharedMemorySize, GEMM_SMEM);
    cudaFuncSetAttribute(out_gemm_kernel<1>, cudaFuncAttributeMaxDynamicSharedMemorySize, GEMM_SMEM);

    wfold_kernel<<<160, 256>>>(W2s, Wsc_s, W2v, Wsc_v);
    nodeprep_kernel<<<296, 256>>>(node_feat, node_attr, W1s, W1v);
    edge_kernel<<<296, 256>>>(edge_sh, edge_basis, Wfc1, Wfc2, edge_idx);

    out_gemm_kernel<0><<<ROWS_S / 64, 256, GEMM_SMEM>>>(out);
    out_gemm_kernel<1><<<ROWS_V / 64, 256, GEMM_SMEM>>>(out);
}

// round 9
// speedup vs baseline: 1.4313x; 1.1061x over previous
#include <cuda_runtime.h>
#include <cstdint>
#include <cstddef>

#define N_NODES 20000
#define N_EDGES 320000
#define EPB 16

#define LOG2_C       0.6931471805599453f
#define INV_SQRT3_C  0.5773502691896258f
#define INV_SQRT8_C  0.35355339059327373f
#define W_SCALE      0.125f
#define INV_MUL_C    0.125f
#define SC_A_C       0.02209708691207961f   // 1/sqrt(128) * 1/sqrt(16)
#define SC_B_C       0.04419417382415922f   // 1/sqrt(512)

#define ROWS_S 20032                         // 313 * 64
#define ROWS_V 60032                         // 938 * 64

// scratch (__device__ globals). Referenced ONLY from device code.
__device__ __align__(1024) float d_sv[(size_t)N_NODES * 256];
__device__ __align__(1024) float d_cat_s[(size_t)ROWS_S * 640];
__device__ __align__(1024) float d_cat_v[(size_t)ROWS_V * 640];
__device__ __align__(1024) float d_Wcat_s[640 * 64];
__device__ __align__(1024) float d_Wcat_v[640 * 64];

__device__ __forceinline__ unsigned smem_u32(const void* p) {
    return (unsigned)__cvta_generic_to_shared(p);
}
__device__ __forceinline__ float4 ld4s(const float* p) {
    return *reinterpret_cast<const float4*>(p);
}
__device__ __forceinline__ void cp_async16(unsigned saddr, const void* gaddr) {
    asm volatile("cp.async.cg.shared.global [%0], [%1], 16;" :: "r"(saddr), "l"(gaddr));
}
__device__ __forceinline__ void cp_commit() {
    asm volatile("cp.async.commit_group;" ::: "memory");
}
template<int NWAIT>
__device__ __forceinline__ void cp_wait() {
    asm volatile("cp.async.wait_group %0;" :: "n"(NWAIT) : "memory");
}

// ---------------------------------------------------------------------------
__global__ void wfold_kernel(const float* __restrict__ W2s, const float* __restrict__ Wsc_s,
                             const float* __restrict__ W2v, const float* __restrict__ Wsc_v)
{
    const int i = blockIdx.x * blockDim.x + threadIdx.x;
    if (i < 8192) {
        d_Wcat_s[i] = W2s[i] * SC_A_C;
        d_Wcat_v[i] = W2v[i] * SC_A_C;
    } else if (i < 40960) {
        d_Wcat_s[i] = Wsc_s[i - 8192] * SC_B_C;
        d_Wcat_v[i] = Wsc_v[i - 8192] * SC_B_C;
    }
}

// ---------------------------------------------------------------------------
// node prep (unchanged from R8)
// ---------------------------------------------------------------------------
__global__ void __launch_bounds__(256)
nodeprep_kernel(const float* __restrict__ node_feat,
                const float* __restrict__ node_attr,
                const float* __restrict__ W1s,
                const float* __restrict__ W1v)
{
    __shared__ float sW1s[4096];
    __shared__ float sW1v[4096];
    __shared__ float sNF[4][256];
    __shared__ float4 sAT[4][2];

    const int tid = threadIdx.x;
    for (int i = tid; i < 4096; i += 256) { sW1s[i] = W1s[i]; sW1v[i] = W1v[i]; }
    __syncthreads();

    const int ngroups = N_NODES / 4;
    for (int g = blockIdx.x; g < ngroups; g += gridDim.x) {
        const int n0 = g * 4;
        __syncthreads();
        for (int i = tid; i < 1024; i += 256) {
            const int nl = i >> 8, j = i & 255;
            sNF[nl][j] = node_feat[(size_t)(n0 + nl) * 256 + j];
        }
        if (tid < 8) {
            const int nl = tid >> 1, j = tid & 1;
            sAT[nl][j] = __ldg(reinterpret_cast<const float4*>(node_attr + (size_t)(n0 + nl) * 8) + j);
        }
        __syncthreads();

        {
            const int nl = tid >> 6, w = tid & 63;
            const int n = n0 + nl;
            float sacc = 0.f, v0a = 0.f, v1a = 0.f, v2a = 0.f;
#pragma unroll
            for (int u = 0; u < 64; ++u) {
                const float ws = sW1s[u * 64 + w];
                const float wvv = sW1v[u * 64 + w];
                sacc = fmaf(sNF[nl][u], ws, sacc);
                v0a  = fmaf(sNF[nl][64 + 3 * u + 0], wvv, v0a);
                v1a  = fmaf(sNF[nl][64 + 3 * u + 1], wvv, v1a);
                v2a  = fmaf(sNF[nl][64 + 3 * u + 2], wvv, v2a);
            }
            float* o = d_sv + (size_t)n * 256;
            o[w] = sacc * INV_MUL_C;
            o[64 + 3 * w + 0] = v0a * INV_MUL_C;
            o[64 + 3 * w + 1] = v1a * INV_MUL_C;
            o[64 + 3 * w + 2] = v2a * INV_MUL_C;
        }

        if (tid < 128) {
            const int nl = tid >> 5, u = tid & 31;
            reinterpret_cast<float4*>(d_cat_s + (size_t)(n0 + nl) * 640)[u] =
                make_float4(0.f, 0.f, 0.f, 0.f);
        }
        for (int i = tid; i < 384; i += 256) {
            const int rr = i >> 5, u = i & 31;
            const int nl = rr / 3, c = rr - 3 * nl;
            reinterpret_cast<float4*>(d_cat_v + ((size_t)(n0 + nl) * 3 + c) * 640)[u] =
                make_float4(0.f, 0.f, 0.f, 0.f);
        }

        for (int i = tid; i < 512; i += 256) {
            const int nl = i >> 7, p4 = i & 127;
            const float a = sNF[nl][p4 >> 1];
            const float4 at = sAT[nl][p4 & 1];
            reinterpret_cast<float4*>(d_cat_s + (size_t)(n0 + nl) * 640 + 128)[p4] =
                make_float4(a * at.x, a * at.y, a * at.z, a * at.w);
        }
        for (int i = tid; i < 1536; i += 256) {
            const int nl = i / 384;
            const int r  = i - nl * 384;
            const int c  = r >> 7, p4 = r & 127;
            const float a = sNF[nl][64 + 3 * (p4 >> 1) + c];
            const float4 at = sAT[nl][p4 & 1];
            reinterpret_cast<float4*>(d_cat_v + ((size_t)(n0 + nl) * 3 + c) * 640 + 128)[p4] =
                make_float4(a * at.x, a * at.y, a * at.z, a * at.w);
        }
    }
}

// ---------------------------------------------------------------------------
// edge kernel v2: EPB=16, cp.async-prefetched edge inputs, 2 barriers/iter.
// dynamic smem layout (floats):
//   sOut  [0,16384)   2*16*512
//   sH    [16384,..)  16*64 = 1024
//   sWfc1 [17408,..)  512
//   sBas  [17920,..)  2*16*8 = 256
//   sShs  [18176,..)  2*16*4 = 128
//   sIdx  [18304,..)  2*16*2 ints = 64
// total 18368 floats = 73472 B  -> 2 CTAs/SM
// ---------------------------------------------------------------------------
#define EDGE_SMEM (18368 * 4)

__global__ void __launch_bounds__(256, 2)
edge_kernel(const float* __restrict__ edge_sh,
            const float* __restrict__ edge_basis,
            const float* __restrict__ Wfc1,
            const float* __restrict__ Wfc2,
            const int*   __restrict__ edge_idx)
{
    extern __shared__ float esm[];
    float* sOut  = esm;
    float* sH    = esm + 16384;
    float* sWfc1 = esm + 17408;
    float* sBas  = esm + 17920;
    float* sShs  = esm + 18176;
    int*   sIdx  = (int*)(esm + 18304);

    const int tid = threadIdx.x;

    float wcol[64];
#pragma unroll
    for (int k = 0; k < 64; ++k) wcol[k] = Wfc2[k * 256 + tid] * W_SCALE;
    for (int i = tid; i < 512; i += 256) sWfc1[i] = Wfc1[i] * INV_SQRT8_C;

    const int niter = N_EDGES / EPB;   // 20000

    // prefetch issuer: tid<56 each moves one 16B chunk
    auto prefetch = [&](int buf, int it_tgt) {
        const size_t e0 = (size_t)it_tgt * EPB;
        if (tid < 32) {
            cp_async16(smem_u32(sBas + buf * 128 + tid * 4), edge_basis + e0 * 8 + tid * 4);
        } else if (tid < 48) {
            cp_async16(smem_u32(sShs + buf * 64 + (tid - 32) * 4), edge_sh + e0 * 4 + (tid - 32) * 4);
        } else if (tid < 56) {
            cp_async16(smem_u32(sIdx + buf * 32 + (tid - 48) * 4), edge_idx + e0 * 2 + (tid - 48) * 4);
        }
    };

    // stage first tile into buf 0
    if (tid < 56) { prefetch(0, blockIdx.x); cp_commit(); cp_wait<0>(); }
    __syncthreads();

    int li = 0;
    for (int it = blockIdx.x; it < niter; it += gridDim.x, ++li) {
        const int cur = li & 1;
        const int r = cur;   // sOut buffer tracks parity too

        // sOut[r] was consumed by the bulk-reduce issued 2 iterations ago
        if (tid < 4 * EPB) asm volatile("cp.async.bulk.wait_group 1;" ::: "memory");

        // prefetch NEXT tile into the other buffer
        {
            const int nit = it + gridDim.x;
            if (tid < 56) {
                if (nit < niter) prefetch(cur ^ 1, nit);
                cp_commit();
            }
        }

        // phase A: h for 16 edges (1024 values, 4 per thread) from staged basis
#pragma unroll
        for (int i = tid; i < EPB * 64; i += 256) {
            const int el = i >> 6, k = i & 63;
            const float* bb = sBas + cur * 128 + el * 8;
            const float4 b0 = ld4s(bb);
            const float4 b1 = ld4s(bb + 4);
            float acc;
            acc = b0.x * sWfc1[0 * 64 + k];
            acc = fmaf(b0.y, sWfc1[1 * 64 + k], acc);
            acc = fmaf(b0.z, sWfc1[2 * 64 + k], acc);
            acc = fmaf(b0.w, sWfc1[3 * 64 + k], acc);
            acc = fmaf(b1.x, sWfc1[4 * 64 + k], acc);
            acc = fmaf(b1.y, sWfc1[5 * 64 + k], acc);
            acc = fmaf(b1.z, sWfc1[6 * 64 + k], acc);
            acc = fmaf(b1.w, sWfc1[7 * 64 + k], acc);
            const float t = __expf(-fabsf(acc));
            sH[el * 64 + k] = fmaxf(acc, 0.f) + __logf(1.f + t) - LOG2_C;
        }
        __syncthreads();

        // phase B: w[col] for 16 edges (col = tid, Wfc2 column in registers)
        float wv[EPB];
#pragma unroll
        for (int q = 0; q < EPB; ++q) wv[q] = 0.f;
#pragma unroll
        for (int k4 = 0; k4 < 16; ++k4) {
#pragma unroll
            for (int q = 0; q < EPB; ++q) {
                const float4 h4 = ld4s(sH + q * 64 + k4 * 4);
                wv[q] = fmaf(h4.x, wcol[4 * k4 + 0], wv[q]);
                wv[q] = fmaf(h4.y, wcol[4 * k4 + 1], wv[q]);
                wv[q] = fmaf(h4.z, wcol[4 * k4 + 2], wv[q]);
                wv[q] = fmaf(h4.w, wcol[4 * k4 + 3], wv[q]);
            }
        }

        // phase C: gather + tensor product -> staging smem
#pragma unroll
        for (int q = 0; q < EPB; ++q) {
            const float w = wv[q];
            const int src = sIdx[cur * 32 + 2 * q + 1];
            const float* nrow = d_sv + (size_t)src * 256;
            const float shx = sShs[cur * 64 + 4 * q + 0];
            const float shy = sShs[cur * 64 + 4 * q + 1];
            const float shz = sShs[cur * 64 + 4 * q + 2];
            const float shw = sShs[cur * 64 + 4 * q + 3];
            float* st = sOut + (r * EPB + q) * 512;
            const int col = tid;
            if (col < 64) {                       // outA -> cat_s agg[0:64]
                st[col] = w * nrow[col] * shx;
            } else if (col < 128) {               // outB: m = u, c-major
                const int u = col - 64;
                const float b = w * nrow[u];
                st[128 + 0 * 128 + u] = b * shy;
                st[128 + 1 * 128 + u] = b * shz;
                st[128 + 2 * 128 + u] = b * shw;
            } else if (col < 192) {               // outC: m = 64+u, c-major
                const int u = col - 128;
                const float ws = w * shx;
                st[128 + 0 * 128 + 64 + u] = ws * nrow[64 + 3 * u + 0];
                st[128 + 1 * 128 + 64 + u] = ws * nrow[64 + 3 * u + 1];
                st[128 + 2 * 128 + 64 + u] = ws * nrow[64 + 3 * u + 2];
            } else {                              // outD -> cat_s agg[64:128]
                const int u = col - 192;
                const float x0 = nrow[64 + 3 * u + 0];
                const float x1 = nrow[64 + 3 * u + 1];
                const float x2 = nrow[64 + 3 * u + 2];
                st[64 + u] = w * INV_SQRT3_C * (x0 * shy + x1 * shz + x2 * shw);
            }
        }

        // ensure next tile's staged inputs have landed before the barrier
        if (tid < 56) cp_wait<0>();
        __syncthreads();

        // 4x 512B bulk reduce-add per edge
        if (tid < 4 * EPB) {
            asm volatile("fence.proxy.async.shared::cta;" ::: "memory");
            const int q = tid >> 2, part = tid & 3;
            const int dst = sIdx[cur * 32 + 2 * q];
            float* g = (part == 0)
                     ? (d_cat_s + (size_t)dst * 640)
                     : (d_cat_v + ((size_t)dst * 3 + (part - 1)) * 640);
            const unsigned saddr = smem_u32(sOut + (r * EPB + q) * 512 + part * 128);
            asm volatile(
                "cp.reduce.async.bulk.global.shared::cta.bulk_group.add.f32 [%0], [%1], %2;"
                :: "l"(g), "r"(saddr), "n"(512) : "memory");
            asm volatile("cp.async.bulk.commit_group;" ::: "memory");
        }
    }
    if (tid < 4 * EPB) asm volatile("cp.async.bulk.wait_group 0;" ::: "memory");
}

// ===========================================================================
// Pipelined register-tiled SGEMM (unchanged from R8)
// ===========================================================================
#define KCH 80
#define PA 84
#define GEMM_SMEM ((2 * 64 * PA + 2 * KCH * 64) * 4)

template<int MODE>
__global__ void __launch_bounds__(256, 2)
out_gemm_kernel(float* __restrict__ out)
{
    const float* __restrict__ A = (MODE == 0) ? d_cat_s  : d_cat_v;
    const float* __restrict__ B = (MODE == 0) ? d_Wcat_s : d_Wcat_v;

    extern __shared__ float sm[];
    float* sA = sm;
    float* sB = sm + 2 * 64 * PA;

    const int tid = threadIdx.x;
    const int tx = tid & 15, ty = tid >> 4;
    const int r0 = blockIdx.x * 64;

    float acc[4][4];
#pragma unroll
    for (int i = 0; i < 4; ++i)
#pragma unroll
        for (int j = 0; j < 4; ++j) acc[i][j] = 0.f;

    auto stage = [&](int buf, int c) {
        const int k0 = c * KCH;
        float* sAb = sA + buf * 64 * PA;
        float* sBb = sB + buf * KCH * 64;
#pragma unroll
        for (int j = 0; j < 5; ++j) {
            const int idx = tid + 256 * j;
            const int row = idx / 20, u = idx - row * 20;
            cp_async16(smem_u32(sAb + row * PA + 4 * u),
                       A + (size_t)(r0 + row) * 640 + k0 + 4 * u);
        }
#pragma unroll
        for (int j = 0; j < 5; ++j) {
            const int idx = tid + 256 * j;
            const int row = idx >> 4, u = idx & 15;
            cp_async16(smem_u32(sBb + row * 64 + 4 * u),
                       B + (size_t)(k0 + row) * 64 + 4 * u);
        }
        cp_commit();
    };

    stage(0, 0);

#pragma unroll 1
    for (int c = 0; c < 8; ++c) {
        if (c < 7) { stage((c + 1) & 1, c + 1); cp_wait<1>(); }
        else       { cp_wait<0>(); }
        __syncthreads();

        const float* pa = sA + (c & 1) * 64 * PA + (4 * ty) * PA;
        const float* pb = sB + (c & 1) * KCH * 64 + 4 * tx;
#pragma unroll 4
        for (int k4 = 0; k4 < KCH / 4; ++k4) {
            const float4 a0 = ld4s(pa + 0 * PA + 4 * k4);
            const float4 a1 = ld4s(pa + 1 * PA + 4 * k4);
            const float4 a2 = ld4s(pa + 2 * PA + 4 * k4);
            const float4 a3 = ld4s(pa + 3 * PA + 4 * k4);
            const float4 b0 = ld4s(pb + (4 * k4 + 0) * 64);
            const float4 b1 = ld4s(pb + (4 * k4 + 1) * 64);
            const float4 b2 = ld4s(pb + (4 * k4 + 2) * 64);
            const float4 b3 = ld4s(pb + (4 * k4 + 3) * 64);

            acc[0][0] = fmaf(a0.x, b0.x, acc[0][0]); acc[0][1] = fmaf(a0.x, b0.y, acc[0][1]);
            acc[0][2] = fmaf(a0.x, b0.z, acc[0][2]); acc[0][3] = fmaf(a0.x, b0.w, acc[0][3]);
            acc[1][0] = fmaf(a1.x, b0.x, acc[1][0]); acc[1][1] = fmaf(a1.x, b0.y, acc[1][1]);
            acc[1][2] = fmaf(a1.x, b0.z, acc[1][2]); acc[1][3] = fmaf(a1.x, b0.w, acc[1][3]);
            acc[2][0] = fmaf(a2.x, b0.x, acc[2][0]); acc[2][1] = fmaf(a2.x, b0.y, acc[2][1]);
            acc[2][2] = fmaf(a2.x, b0.z, acc[2][2]); acc[2][3] = fmaf(a2.x, b0.w, acc[2][3]);
            acc[3][0] = fmaf(a3.x, b0.x, acc[3][0]); acc[3][1] = fmaf(a3.x, b0.y, acc[3][1]);
            acc[3][2] = fmaf(a3.x, b0.z, acc[3][2]); acc[3][3] = fmaf(a3.x, b0.w, acc[3][3]);

            acc[0][0] = fmaf(a0.y, b1.x, acc[0][0]); acc[0][1] = fmaf(a0.y, b1.y, acc[0][1]);
            acc[0][2] = fmaf(a0.y, b1.z, acc[0][2]); acc[0][3] = fmaf(a0.y, b1.w, acc[0][3]);
            acc[1][0] = fmaf(a1.y, b1.x, acc[1][0]); acc[1][1] = fmaf(a1.y, b1.y, acc[1][1]);
            acc[1][2] = fmaf(a1.y, b1.z, acc[1][2]); acc[1][3] = fmaf(a1.y, b1.w, acc[1][3]);
            acc[2][0] = fmaf(a2.y, b1.x, acc[2][0]); acc[2][1] = fmaf(a2.y, b1.y, acc[2][1]);
            acc[2][2] = fmaf(a2.y, b1.z, acc[2][2]); acc[2][3] = fmaf(a2.y, b1.w, acc[2][3]);
            acc[3][0] = fmaf(a3.y, b1.x, acc[3][0]); acc[3][1] = fmaf(a3.y, b1.y, acc[3][1]);
            acc[3][2] = fmaf(a3.y, b1.z, acc[3][2]); acc[3][3] = fmaf(a3.y, b1.w, acc[3][3]);

            acc[0][0] = fmaf(a0.z, b2.x, acc[0][0]); acc[0][1] = fmaf(a0.z, b2.y, acc[0][1]);
            acc[0][2] = fmaf(a0.z, b2.z, acc[0][2]); acc[0][3] = fmaf(a0.z, b2.w, acc[0][3]);
            acc[1][0] = fmaf(a1.z, b2.x, acc[1][0]); acc[1][1] = fmaf(a1.z, b2.y, acc[1][1]);
            acc[1][2] = fmaf(a1.z, b2.z, acc[1][2]); acc[1][3] = fmaf(a1.z, b2.w, acc[1][3]);
            acc[2][0] = fmaf(a2.z, b2.x, acc[2][0]); acc[2][1] = fmaf(a2.z, b2.y, acc[2][1]);
            acc[2][2] = fmaf(a2.z, b2.z, acc[2][2]); acc[2][3] = fmaf(a2.z, b2.w, acc[2][3]);
            acc[3][0] = fmaf(a3.z, b2.x, acc[3][0]); acc[3][1] = fmaf(a3.z, b2.y, acc[3][1]);
            acc[3][2] = fmaf(a3.z, b2.z, acc[3][2]); acc[3][3] = fmaf(a3.z, b2.w, acc[3][3]);

            acc[0][0] = fmaf(a0.w, b3.x, acc[0][0]); acc[0][1] = fmaf(a0.w, b3.y, acc[0][1]);
            acc[0][2] = fmaf(a0.w, b3.z, acc[0][2]); acc[0][3] = fmaf(a0.w, b3.w, acc[0][3]);
            acc[1][0] = fmaf(a1.w, b3.x, acc[1][0]); acc[1][1] = fmaf(a1.w, b3.y, acc[1][1]);
            acc[1][2] = fmaf(a1.w, b3.z, acc[1][2]); acc[1][3] = fmaf(a1.w, b3.w, acc[1][3]);
            acc[2][0] = fmaf(a2.w, b3.x, acc[2][0]); acc[2][1] = fmaf(a2.w, b3.y, acc[2][1]);
            acc[2][2] = fmaf(a2.w, b3.z, acc[2][2]); acc[2][3] = fmaf(a2.w, b3.w, acc[2][3]);
            acc[3][0] = fmaf(a3.w, b3.x, acc[3][0]); acc[3][1] = fmaf(a3.w, b3.y, acc[3][1]);
            acc[3][2] = fmaf(a3.w, b3.z, acc[3][2]); acc[3][3] = fmaf(a3.w, b3.w, acc[3][3]);
        }
        __syncthreads();
    }

#pragma unroll
    for (int r = 0; r < 4; ++r) {
        const int grow = r0 + 4 * ty + r;
        if (MODE == 0) {
            if (grow < N_NODES) {
                float4 v = make_float4(acc[r][0], acc[r][1], acc[r][2], acc[r][3]);
                *reinterpret_cast<float4*>(out + (size_t)grow * 256 + 4 * tx) = v;
            }
        } else {
            if (grow < 3 * N_NODES) {
                const int n = grow / 3, cc = grow - 3 * (grow / 3);
                float* o = out + (size_t)n * 256 + 64 + cc;
#pragma unroll
                for (int j = 0; j < 4; ++j) o[3 * (4 * tx + j)] = acc[r][j];
            }
        }
    }
}

// ---------------------------------------------------------------------------
extern "C" void kernel_launch(void* const* d_in, const int* /*in_sizes*/, int /*n_in*/,
                              void* d_out, int /*out_size*/)
{
    const float* node_feat  = (const float*)d_in[0];
    const float* node_attr  = (const float*)d_in[1];
    const float* edge_sh    = (const float*)d_in[2];
    const float* edge_basis = (const float*)d_in[3];
    const float* W1s        = (const float*)d_in[4];
    const float* W1v        = (const float*)d_in[5];
    const float* Wfc1       = (const float*)d_in[6];
    const float* Wfc2       = (const float*)d_in[7];
    const float* W2s        = (const float*)d_in[8];
    const float* W2v        = (const float*)d_in[9];
    const float* Wsc_s      = (const float*)d_in[10];
    const float* Wsc_v      = (const float*)d_in[11];
    const int*   edge_idx   = (const int*)d_in[12];
    float* out = (float*)d_out;

    cudaFuncSetAttribute(edge_kernel, cudaFuncAttributeMaxDynamicSharedMemorySize, EDGE_SMEM);
    cudaFuncSetAttribute(out_gemm_kernel<0>, cudaFuncAttributeMaxDynamicSharedMemorySize, GEMM_SMEM);
    cudaFuncSetAttribute(out_gemm_kernel<1>, cudaFuncAttributeMaxDynamicSharedMemorySize, GEMM_SMEM);

    wfold_kernel<<<160, 256>>>(W2s, Wsc_s, W2v, Wsc_v);
    nodeprep_kernel<<<296, 256>>>(node_feat, node_attr, W1s, W1v);
    edge_kernel<<<296, 256, EDGE_SMEM>>>(edge_sh, edge_basis, Wfc1, Wfc2, edge_idx);

    out_gemm_kernel<0><<<ROWS_S / 64, 256, GEMM_SMEM>>>(out);
    out_gemm_kernel<1><<<ROWS_V / 64, 256, GEMM_SMEM>>>(out);
}